// round 4
// baseline (speedup 1.0000x reference)
#include <cuda_runtime.h>

#define BB 256
#define TT 2048
#define HH 128
#define FC1N 64
#define RING 32
#define RPAD 132    // ring row stride in floats (16B-aligned, FC reads 4-way)

// dynamic SMEM layout (float offsets)
#define OFF_XA    0
#define OFF_XB    (TT * 3)
#define OFF_RA    (2 * TT * 3)                // ring A
#define OFF_RB    (OFF_RA + RING * RPAD)      // ring B
#define OFF_WC    (OFF_RB + RING * RPAD)      // [3][HH]
#define OFF_PA    (OFF_WC + 3 * HH)           // [4][96]
#define OFF_PB    (OFF_PA + 4 * 96)
#define OFF_BC    (OFF_PB + 4 * 96)
#define SMEM_FLOATS (OFF_BC + 4)

__device__ __forceinline__ unsigned long long fma2(unsigned long long a,
                                                   unsigned long long b,
                                                   unsigned long long c) {
    unsigned long long d;
    asm("fma.rn.f32x2 %0, %1, %2, %3;" : "=l"(d) : "l"(a), "l"(b), "l"(c));
    return d;
}
__device__ __forceinline__ unsigned long long add2(unsigned long long a,
                                                   unsigned long long b) {
    unsigned long long d;
    asm("add.rn.f32x2 %0, %1, %2;" : "=l"(d) : "l"(a), "l"(b));
    return d;
}
__device__ __forceinline__ float2 unpack2(unsigned long long v) {
    float2 r;
    asm("mov.b64 {%0, %1}, %2;" : "=f"(r.x), "=f"(r.y) : "l"(v));
    return r;
}
__device__ __forceinline__ float tanh_fast(float x) {
    float y;
    asm("tanh.approx.f32 %0, %1;" : "=f"(y) : "f"(x));
    return y;
}

__global__ __launch_bounds__(128, 1)
void rnn_fused2_kernel(const float* __restrict__ x,
                       const float* __restrict__ hidden,
                       const float* __restrict__ W_ih,
                       const float* __restrict__ W_hh,
                       const float* __restrict__ b_ih,
                       const float* __restrict__ b_hh,
                       const float* __restrict__ W_fc1,
                       const float* __restrict__ b_fc1,
                       const float* __restrict__ W_fc2,
                       const float* __restrict__ b_fc2,
                       float* __restrict__ out)
{
    extern __shared__ __align__(16) float sm[];
    float* xA    = sm + OFF_XA;
    float* xB    = sm + OFF_XB;
    float* ringA = sm + OFF_RA;
    float* ringB = sm + OFF_RB;
    float* wc    = sm + OFF_WC;
    float* pA    = sm + OFF_PA;
    float* pB    = sm + OFF_PB;
    float* bc    = sm + OFF_BC;

    const int j  = threadIdx.x;
    const int rA = 2 * blockIdx.x;
    const int rB = rA + 1;

    // ---- preload x for both rows (coalesced float4) ----
    {
        const float4* ga = (const float4*)(x + (size_t)rA * TT * 3);
        const float4* gb = (const float4*)(x + (size_t)rB * TT * 3);
        float4* sa = (float4*)xA;
        float4* sb = (float4*)xB;
        #pragma unroll
        for (int i = 0; i < (TT * 3 / 4) / HH; i++) {
            sa[i * HH + j] = ga[i * HH + j];
            sb[i * HH + j] = gb[i * HH + j];
        }
    }

    // ---- W_hh row j as packed f32x2 (128 regs, shared by both rows) ----
    unsigned long long w[HH / 2];
    {
        const unsigned long long* wg = (const unsigned long long*)(W_hh + j * HH);
        #pragma unroll
        for (int i = 0; i < HH / 2; i++) w[i] = wg[i];
    }

    const float wih0 = W_ih[j * 3 + 0];
    const float wih1 = W_ih[j * 3 + 1];
    const float wih2 = W_ih[j * 3 + 2];
    const float bias = b_ih[j] + b_hh[j];

    // ---- collapsed FC head: wc[o][j] = sum_f W_fc2[o][f]*W_fc1[f][j] ----
    {
        float c0 = 0.f, c1 = 0.f, c2 = 0.f;
        #pragma unroll 4
        for (int f = 0; f < FC1N; f++) {
            float v = W_fc1[f * HH + j];
            c0 = fmaf(W_fc2[0 * FC1N + f], v, c0);
            c1 = fmaf(W_fc2[1 * FC1N + f], v, c1);
            c2 = fmaf(W_fc2[2 * FC1N + f], v, c2);
        }
        wc[0 * HH + j] = c0; wc[1 * HH + j] = c1; wc[2 * HH + j] = c2;
    }
    if (j < 3) {
        float s = 0.f;
        #pragma unroll 8
        for (int f = 0; f < FC1N; f++)
            s = fmaf(W_fc2[j * FC1N + f], b_fc1[f], s);
        bc[j] = s + b_fc2[j];
    }

    // initial hidden state in slot RING-1 (t = -1)
    ringA[(RING - 1) * RPAD + j] = hidden[rA * HH + j];
    ringB[(RING - 1) * RPAD + j] = hidden[rB * HH + j];
    __syncthreads();

    const int kg = j >> 5;     // FC k-group
    const int tl = j & 31;     // FC local timestep
    float* outA = out + (size_t)rA * TT * 3;
    float* outB = out + (size_t)rB * TT * 3;

    float hvA = 0.f, hvB = 0.f;

    for (int tc = 0; tc < TT / RING; tc++) {
        #pragma unroll 1
        for (int ts = 0; ts < RING; ts++) {
            const int t = tc * RING + ts;

            // x projections (independent of h)
            const float xa0 = xA[3 * t + 0], xa1 = xA[3 * t + 1], xa2 = xA[3 * t + 2];
            const float xb0 = xB[3 * t + 0], xb1 = xB[3 * t + 1], xb2 = xB[3 * t + 2];
            float xpA = fmaf(xa2, wih2, fmaf(xa1, wih1, fmaf(xa0, wih0, bias)));
            float xpB = fmaf(xb2, wih2, fmaf(xb1, wih1, fmaf(xb0, wih0, bias)));

            // two independent 128-wide dots, 8 interleaved fma2 chains
            const int ps = ((ts - 1) & (RING - 1)) * RPAD;
            const ulonglong2* hpA = (const ulonglong2*)(ringA + ps);
            const ulonglong2* hpB = (const ulonglong2*)(ringB + ps);
            unsigned long long a0 = 0ull, a1 = 0ull, a2 = 0ull, a3 = 0ull;
            unsigned long long c0 = 0ull, c1 = 0ull, c2 = 0ull, c3 = 0ull;
            #pragma unroll
            for (int i = 0; i < 16; i++) {
                ulonglong2 ha = hpA[2 * i];
                ulonglong2 hb = hpA[2 * i + 1];
                ulonglong2 ka = hpB[2 * i];
                ulonglong2 kb = hpB[2 * i + 1];
                a0 = fma2(w[4 * i + 0], ha.x, a0);
                c0 = fma2(w[4 * i + 0], ka.x, c0);
                a1 = fma2(w[4 * i + 1], ha.y, a1);
                c1 = fma2(w[4 * i + 1], ka.y, c1);
                a2 = fma2(w[4 * i + 2], hb.x, a2);
                c2 = fma2(w[4 * i + 2], kb.x, c2);
                a3 = fma2(w[4 * i + 3], hb.y, a3);
                c3 = fma2(w[4 * i + 3], kb.y, c3);
            }
            unsigned long long sA = add2(add2(a0, a1), add2(a2, a3));
            unsigned long long sB = add2(add2(c0, c1), add2(c2, c3));
            float2 fA = unpack2(sA);
            float2 fB = unpack2(sB);

            hvA = tanh_fast(xpA + (fA.x + fA.y));
            hvB = tanh_fast(xpB + (fB.x + fB.y));
            ringA[ts * RPAD + j] = hvA;
            ringB[ts * RPAD + j] = hvB;
            __syncthreads();
        }

        // ---- amortized FC drain: slots 0..31 -> timesteps tc*32 .. +31 ----
        {
            const float4* w0 = (const float4*)(wc + 0 * HH + kg * 32);
            const float4* w1 = (const float4*)(wc + 1 * HH + kg * 32);
            const float4* w2 = (const float4*)(wc + 2 * HH + kg * 32);
            const float4* hA = (const float4*)(ringA + tl * RPAD + kg * 32);
            const float4* hB = (const float4*)(ringB + tl * RPAD + kg * 32);
            float qa0 = 0.f, qa1 = 0.f, qa2 = 0.f;
            float qb0 = 0.f, qb1 = 0.f, qb2 = 0.f;
            #pragma unroll
            for (int i = 0; i < 8; i++) {
                float4 va = hA[i], vb = hB[i];
                float4 u0 = w0[i], u1 = w1[i], u2 = w2[i];
                qa0 = fmaf(va.x, u0.x, fmaf(va.y, u0.y, fmaf(va.z, u0.z, fmaf(va.w, u0.w, qa0))));
                qa1 = fmaf(va.x, u1.x, fmaf(va.y, u1.y, fmaf(va.z, u1.z, fmaf(va.w, u1.w, qa1))));
                qa2 = fmaf(va.x, u2.x, fmaf(va.y, u2.y, fmaf(va.z, u2.z, fmaf(va.w, u2.w, qa2))));
                qb0 = fmaf(vb.x, u0.x, fmaf(vb.y, u0.y, fmaf(vb.z, u0.z, fmaf(vb.w, u0.w, qb0))));
                qb1 = fmaf(vb.x, u1.x, fmaf(vb.y, u1.y, fmaf(vb.z, u1.z, fmaf(vb.w, u1.w, qb1))));
                qb2 = fmaf(vb.x, u2.x, fmaf(vb.y, u2.y, fmaf(vb.z, u2.z, fmaf(vb.w, u2.w, qb2))));
            }
            pA[kg * 96 + tl * 3 + 0] = qa0;
            pA[kg * 96 + tl * 3 + 1] = qa1;
            pA[kg * 96 + tl * 3 + 2] = qa2;
            pB[kg * 96 + tl * 3 + 0] = qb0;
            pB[kg * 96 + tl * 3 + 1] = qb1;
            pB[kg * 96 + tl * 3 + 2] = qb2;
            __syncthreads();

            if (j < 96) {
                const float bcv = bc[j % 3];
                const size_t o = (size_t)(tc * RING) * 3 + j;
                outA[o] = pA[j] + pA[96 + j] + pA[192 + j] + pA[288 + j] + bcv;
                outB[o] = pB[j] + pB[96 + j] + pB[192 + j] + pB[288 + j] + bcv;
            }
            // next chunk's ring-slot-0 write is ordered after the barrier above;
            // partial arrays are re-written only after 32 more per-step barriers.
        }
    }

    // final hidden states
    out[(size_t)BB * TT * 3 + rA * HH + j] = hvA;
    out[(size_t)BB * TT * 3 + rB * HH + j] = hvB;
}

extern "C" void kernel_launch(void* const* d_in, const int* in_sizes, int n_in,
                              void* d_out, int out_size) {
    const float* x      = (const float*)d_in[0];
    const float* hidden = (const float*)d_in[1];
    const float* W_ih   = (const float*)d_in[2];
    const float* W_hh   = (const float*)d_in[3];
    const float* b_ih   = (const float*)d_in[4];
    const float* b_hh   = (const float*)d_in[5];
    const float* W_fc1  = (const float*)d_in[6];
    const float* b_fc1  = (const float*)d_in[7];
    const float* W_fc2  = (const float*)d_in[8];
    const float* b_fc2  = (const float*)d_in[9];
    float* out = (float*)d_out;

    const int smem_bytes = SMEM_FLOATS * sizeof(float);
    static bool attr_set = false;
    if (!attr_set) {
        cudaFuncSetAttribute(rnn_fused2_kernel,
                             cudaFuncAttributeMaxDynamicSharedMemorySize,
                             smem_bytes);
        attr_set = true;
    }
    rnn_fused2_kernel<<<BB / 2, HH, smem_bytes>>>(
        x, hidden, W_ih, W_hh, b_ih, b_hh,
        W_fc1, b_fc1, W_fc2, b_fc2, out);
}